// round 9
// baseline (speedup 1.0000x reference)
#include <cuda_runtime.h>
#include <cuda_bf16.h>
#include <cstdint>
#include <cstddef>

constexpr int Bc = 2, Sq = 2048, HIDc = 4096, NHc = 32, NKVc = 8, HDc = 128;
constexpr int Kd = 4096;

__device__ float g_Q[(size_t)Bc * NHc * Sq * HDc];
__device__ float g_K[(size_t)Bc * NKVc * Sq * HDc];
__device__ float g_V[(size_t)Bc * NKVc * Sq * HDc];
__device__ float g_ctx[(size_t)Bc * Sq * NHc * HDc];
__device__ __nv_bfloat16 g_Ahi[(size_t)4096 * Kd];
__device__ __nv_bfloat16 g_Alo[(size_t)4096 * Kd];
__device__ __nv_bfloat16 g_Bhi[(size_t)4096 * Kd];
__device__ __nv_bfloat16 g_Blo[(size_t)4096 * Kd];

// ---------------------------------------------------------------------------
__device__ __forceinline__ uint32_t smem_u32(const void* p) {
    uint32_t a;
    asm("{ .reg .u64 t; cvta.to.shared.u64 t, %1; cvt.u32.u64 %0, t; }" : "=r"(a) : "l"(p));
    return a;
}
__device__ __forceinline__ float2 ffma2(float2 a, float2 b, float2 c) {
    unsigned long long ua = *reinterpret_cast<unsigned long long*>(&a);
    unsigned long long ub = *reinterpret_cast<unsigned long long*>(&b);
    unsigned long long uc = *reinterpret_cast<unsigned long long*>(&c);
    unsigned long long ud;
    asm("fma.rn.f32x2 %0, %1, %2, %3;" : "=l"(ud) : "l"(ua), "l"(ub), "l"(uc));
    return *reinterpret_cast<float2*>(&ud);
}
__device__ __forceinline__ void cp16(uint32_t d, const void* g) {
    asm volatile("cp.async.cg.shared.global [%0], [%1], 16;" :: "r"(d), "l"(g));
}
__device__ __forceinline__ void ldm4(uint32_t* r, uint32_t a) {
    asm volatile("ldmatrix.sync.aligned.m8n8.x4.shared.b16 {%0,%1,%2,%3}, [%4];"
        : "=r"(r[0]), "=r"(r[1]), "=r"(r[2]), "=r"(r[3]) : "r"(a));
}
__device__ __forceinline__ void mma16816(float* c, const uint32_t* a, uint32_t b0, uint32_t b1) {
    asm volatile("mma.sync.aligned.m16n8k16.row.col.f32.bf16.bf16.f32 "
        "{%0,%1,%2,%3}, {%4,%5,%6,%7}, {%8,%9}, {%0,%1,%2,%3};"
        : "+f"(c[0]), "+f"(c[1]), "+f"(c[2]), "+f"(c[3])
        : "r"(a[0]), "r"(a[1]), "r"(a[2]), "r"(a[3]), "r"(b0), "r"(b1));
}

// ---------------------------------------------------------------------------
__global__ void split_kernel(const float* __restrict__ x, __nv_bfloat16* __restrict__ hi,
                             __nv_bfloat16* __restrict__ lo, size_t off, size_t cnt)
{
    size_t i = off + ((size_t)blockIdx.x * blockDim.x + threadIdx.x) * 4;
    if (i >= off + cnt) return;
    float4 v = *reinterpret_cast<const float4*>(x + i);
    __nv_bfloat16 h0 = __float2bfloat16(v.x), h1 = __float2bfloat16(v.y);
    __nv_bfloat16 h2 = __float2bfloat16(v.z), h3 = __float2bfloat16(v.w);
    *reinterpret_cast<__nv_bfloat162*>(hi + i)     = {h0, h1};
    *reinterpret_cast<__nv_bfloat162*>(hi + i + 2) = {h2, h3};
    *reinterpret_cast<__nv_bfloat162*>(lo + i) =
        {__float2bfloat16(v.x - __bfloat162float(h0)),
         __float2bfloat16(v.y - __bfloat162float(h1))};
    *reinterpret_cast<__nv_bfloat162*>(lo + i + 2) =
        {__float2bfloat16(v.z - __bfloat162float(h2)),
         __float2bfloat16(v.w - __bfloat162float(h3))};
}

// ---------------------------------------------------------------------------
__global__ void tsplit_kernel(const float* __restrict__ W, __nv_bfloat16* __restrict__ Thi,
                              __nv_bfloat16* __restrict__ Tlo, int N)
{
    __shared__ float t[32][33];
    int n0 = blockIdx.x * 32, k0 = blockIdx.y * 32;
    int tx = threadIdx.x, ty = threadIdx.y;
#pragma unroll
    for (int j = 0; j < 4; j++)
        t[ty + 8 * j][tx] = W[(size_t)(k0 + ty + 8 * j) * N + n0 + tx];
    __syncthreads();
#pragma unroll
    for (int j = 0; j < 4; j++) {
        float v = t[tx][ty + 8 * j];
        __nv_bfloat16 h = __float2bfloat16(v);
        size_t idx = (size_t)(n0 + ty + 8 * j) * Kd + k0 + tx;
        Thi[idx] = h;
        Tlo[idx] = __float2bfloat16(v - __bfloat162float(h));
    }
}

// ---------------------------------------------------------------------------
// bf16 mma.sync GEMM over virtual K' = 3*4096, spill-free geometry:
// 512 threads, 16 warps, warp tile 32x32 (4x4 warp grid on BM=BN=128).
// Frag software pipelining: frags for chunk kc+1 loaded at end of iter kc.
// 4 cp.async stages. ~85 regs/thread -> no spills at 512 thr/SM.
// ---------------------------------------------------------------------------
constexpr int GSTAGE = 20480;
constexpr int GNSTG  = 4;
constexpr int GSMEM  = GNSTG * GSTAGE;  // 81920

template <int MODE>
__global__ __launch_bounds__(512, 1)
void gemm_mma(const __nv_bfloat16* __restrict__ Ahi, const __nv_bfloat16* __restrict__ Alo,
              const __nv_bfloat16* __restrict__ Bhi, const __nv_bfloat16* __restrict__ Blo,
              const float* __restrict__ bias, float* __restrict__ C, int N, int heads)
{
    extern __shared__ __align__(16) char smc[];
    const uint32_t sbase = smem_u32(smc);
    const int tid = threadIdx.x;
    const int warp = tid >> 5, lane = tid & 31;
    const int m0 = blockIdx.y * 128, n0 = blockIdx.x * 128;
    constexpr int NKI = 3 * (Kd / 32);  // 384 virtual chunks

    auto issue = [&](int kc) {
        const int buf = kc % GNSTG;
        const uint32_t sb = sbase + buf * GSTAGE;
        const int seg = kc >> 7;
        const int k0 = (kc & 127) * 32;
        const __nv_bfloat16* Aseg = (seg == 1) ? Alo : Ahi;
        const __nv_bfloat16* Bseg = (seg == 2) ? Blo : Bhi;
#pragma unroll
        for (int j = 0; j < 2; j++) {
            int task = tid + j * 512;
            if (task < 512) {
                int row = task >> 2, ch = task & 3;
                cp16(sb + row * 80 + ch * 16,
                     Aseg + (size_t)(m0 + row) * Kd + k0 + ch * 8);
            } else {
                int t2 = task - 512;
                int row = t2 >> 2, ch = t2 & 3;
                cp16(sb + 10240 + row * 80 + ch * 16,
                     Bseg + (size_t)(n0 + row) * Kd + k0 + ch * 8);
            }
        }
        asm volatile("cp.async.commit_group;" ::: "memory");
    };

    const int wm = (warp >> 2) * 32, wn = (warp & 3) * 32;

    uint32_t fa[2][2][4];  // [ks][mi][4]
    uint32_t fb[2][2][4];  // [ks][nb][4]

    auto ldfrags = [&](int buf) {
        const uint32_t sA = sbase + buf * GSTAGE;
        const uint32_t sB = sA + 10240;
#pragma unroll
        for (int ks = 0; ks < 2; ks++) {
            const int kb = ks * 32;
#pragma unroll
            for (int mi = 0; mi < 2; mi++)
                ldm4(fa[ks][mi], sA + (wm + mi * 16 + (lane & 15)) * 80 + kb + (lane >> 4) * 16);
#pragma unroll
            for (int nb = 0; nb < 2; nb++)
                ldm4(fb[ks][nb], sB + (wn + nb * 16 + ((lane >> 4) << 3) + (lane & 7)) * 80
                                   + kb + ((lane >> 3) & 1) * 16);
        }
    };

    float acc[2][4][4];
#pragma unroll
    for (int mi = 0; mi < 2; mi++)
#pragma unroll
        for (int ni = 0; ni < 4; ni++)
#pragma unroll
            for (int r = 0; r < 4; r++) acc[mi][ni][r] = 0.f;

    issue(0);
    issue(1);
    issue(2);
    asm volatile("cp.async.wait_group 2;" ::: "memory");
    __syncthreads();
    ldfrags(0);
    issue(3);

    for (int kc = 0; kc < NKI; kc++) {
        // 16 MMAs on held fragments
#pragma unroll
        for (int ks = 0; ks < 2; ks++)
#pragma unroll
            for (int mi = 0; mi < 2; mi++)
#pragma unroll
                for (int ni = 0; ni < 4; ni++)
                    mma16816(acc[mi][ni], fa[ks][mi],
                             fb[ks][ni >> 1][2 * (ni & 1)], fb[ks][ni >> 1][2 * (ni & 1) + 1]);

        if (kc + 1 < NKI) {
            asm volatile("cp.async.wait_group 2;" ::: "memory");
            __syncthreads();
            ldfrags((kc + 1) % GNSTG);
            if (kc + 4 < NKI) issue(kc + 4);
        }
    }

    // Epilogue
#pragma unroll
    for (int mi = 0; mi < 2; mi++) {
#pragma unroll
        for (int rg = 0; rg < 2; rg++) {
            const int m = m0 + wm + mi * 16 + rg * 8 + (lane >> 2);
            const int bidx = m >> 11, sidx = m & 2047;
#pragma unroll
            for (int ni = 0; ni < 4; ni++) {
                const int col = n0 + wn + ni * 8 + (lane & 3) * 2;
                float v0 = acc[mi][ni][rg * 2 + 0];
                float v1 = acc[mi][ni][rg * 2 + 1];
                float* dst;
                if (MODE == 0) {
                    dst = C + (size_t)m * N + col;
                } else {
                    v0 += __ldg(bias + col);
                    v1 += __ldg(bias + col + 1);
                    int h = col >> 7, d = col & 127;
                    dst = C + (((size_t)bidx * heads + h) * Sq + sidx) * HDc + d;
                }
                *reinterpret_cast<float2*>(dst) = make_float2(v0, v1);
            }
        }
    }
}

// ---------------------------------------------------------------------------
__global__ void rope_kernel(float* __restrict__ x, const float* __restrict__ cosp,
                            const float* __restrict__ sinp, int heads, int total)
{
    int i = blockIdx.x * blockDim.x + threadIdx.x;
    if (i >= total) return;
    int dd = i & 63;
    int s = (i >> 6) & 2047;
    int bh = i >> 17;
    int h = bh % heads, b = bh / heads;
    size_t base = (((size_t)b * heads + h) * Sq + s) * HDc;
    size_t cbase = ((size_t)b * Sq + s) * HDc;
    float x1 = x[base + dd], x2 = x[base + dd + 64];
    float c1 = cosp[cbase + dd], c2 = cosp[cbase + dd + 64];
    float s1 = sinp[cbase + dd], s2 = sinp[cbase + dd + 64];
    x[base + dd]      = x1 * c1 - x2 * s1;
    x[base + dd + 64] = x2 * c2 + x1 * s2;
}

// ---------------------------------------------------------------------------
constexpr int FL_SMEM = (128 * 132 * 2 + 128 * 128) * 4;

__global__ __launch_bounds__(256, 1)
void flash_kernel(const float* __restrict__ Q, const float* __restrict__ Kg,
                  const float* __restrict__ Vg, float* __restrict__ ctx)
{
    constexpr int ST = 132;
    extern __shared__ __align__(16) float sm[];
    float* Qs = sm;
    float* Ks = sm + 128 * ST;
    float* Ps = Ks;
    float* Vs = sm + 2 * 128 * ST;

    const int tid = threadIdx.x;
    const int ti = tid >> 4, tn = tid & 15;
    const int b = blockIdx.z, h = blockIdx.y;
    const int kvh = h >> 2;
    const int q0 = blockIdx.x * 128;

    const float* qptr = Q  + (((size_t)b * NHc  + h)   * Sq + q0) * (size_t)HDc;
    const float* kptr = Kg + (((size_t)b * NKVc + kvh) * Sq) * (size_t)HDc;
    const float* vptr = Vg + (((size_t)b * NKVc + kvh) * Sq) * (size_t)HDc;

#pragma unroll
    for (int i = 0; i < 16; i++) {
        int idx = tid + i * 256;
        int r = idx >> 5, c = (idx & 31) * 4;
        float4 q4 = *reinterpret_cast<const float4*>(qptr + (size_t)r * HDc + c);
        Qs[r * ST + c] = q4.x; Qs[r * ST + c + 1] = q4.y;
        Qs[r * ST + c + 2] = q4.z; Qs[r * ST + c + 3] = q4.w;
    }

    float2 O2[8][4];
    float mrow[8], lrow[8];
#pragma unroll
    for (int i = 0; i < 8; i++) {
        mrow[i] = -1e30f; lrow[i] = 0.f;
#pragma unroll
        for (int c = 0; c < 4; c++) O2[i][c] = make_float2(0.f, 0.f);
    }

    const float scale = 0.08838834764831845f;

    for (int n0 = 0; n0 < Sq; n0 += 128) {
        __syncthreads();
#pragma unroll
        for (int i = 0; i < 16; i++) {
            int idx = tid + i * 256;
            int r = idx >> 5, c = (idx & 31) * 4;
            float4 k4 = *reinterpret_cast<const float4*>(kptr + (size_t)(n0 + r) * HDc + c);
            Ks[r * ST + c] = k4.x; Ks[r * ST + c + 1] = k4.y;
            Ks[r * ST + c + 2] = k4.z; Ks[r * ST + c + 3] = k4.w;
            *reinterpret_cast<float4*>(Vs + r * 128 + c) =
                *reinterpret_cast<const float4*>(vptr + (size_t)(n0 + r) * HDc + c);
        }
        __syncthreads();

        float2 s2[8][4];
#pragma unroll
        for (int i = 0; i < 8; i++)
#pragma unroll
            for (int c = 0; c < 4; c++) s2[i][c] = make_float2(0.f, 0.f);

        for (int d = 0; d < HDc; d += 4) {
            float4 q4[8];
#pragma unroll
            for (int i = 0; i < 8; i++)
                q4[i] = *reinterpret_cast<const float4*>(&Qs[(8 * ti + i) * ST + d]);
#pragma unroll
            for (int c = 0; c < 4; c++) {
                float4 ka = *reinterpret_cast<const float4*>(&Ks[(tn + 16 * (2 * c)) * ST + d]);
                float4 kb = *reinterpret_cast<const float4*>(&Ks[(tn + 16 * (2 * c + 1)) * ST + d]);
#pragma unroll
                for (int i = 0; i < 8; i++) {
                    s2[i][c] = ffma2(make_float2(q4[i].x, q4[i].x), make_float2(ka.x, kb.x), s2[i][c]);
                    s2[i][c] = ffma2(make_float2(q4[i].y, q4[i].y), make_float2(ka.y, kb.y), s2[i][c]);
                    s2[i][c] = ffma2(make_float2(q4[i].z, q4[i].z), make_float2(ka.z, kb.z), s2[i][c]);
                    s2[i][c] = ffma2(make_float2(q4[i].w, q4[i].w), make_float2(ka.w, kb.w), s2[i][c]);
                }
            }
        }

        float corr[8];
#pragma unroll
        for (int i = 0; i < 8; i++) {
            float mt = fmaxf(fmaxf(fmaxf(s2[i][0].x, s2[i][0].y), fmaxf(s2[i][1].x, s2[i][1].y)),
                             fmaxf(fmaxf(s2[i][2].x, s2[i][2].y), fmaxf(s2[i][3].x, s2[i][3].y)));
            mt *= scale;
#pragma unroll
            for (int off = 1; off < 16; off <<= 1)
                mt = fmaxf(mt, __shfl_xor_sync(0xffffffffu, mt, off));
            float mnew = fmaxf(mrow[i], mt);
            corr[i] = __expf(mrow[i] - mnew);
            mrow[i] = mnew;
        }
#pragma unroll
        for (int i = 0; i < 8; i++) {
            float sum = 0.f;
#pragma unroll
            for (int c = 0; c < 4; c++) {
                float px = __expf(s2[i][c].x * scale - mrow[i]);
                float py = __expf(s2[i][c].y * scale - mrow[i]);
                s2[i][c].x = px; s2[i][c].y = py;
                sum += px + py;
            }
#pragma unroll
            for (int off = 1; off < 16; off <<= 1)
                sum += __shfl_xor_sync(0xffffffffu, sum, off);
            lrow[i] = lrow[i] * corr[i] + sum;
        }

        __syncthreads();

#pragma unroll
        for (int i = 0; i < 8; i++) {
            int r = 8 * ti + i;
#pragma unroll
            for (int c = 0; c < 4; c++) {
                Ps[r * ST + tn + 16 * (2 * c)]     = s2[i][c].x;
                Ps[r * ST + tn + 16 * (2 * c + 1)] = s2[i][c].y;
            }
        }
        __syncwarp();

#pragma unroll
        for (int i = 0; i < 8; i++)
#pragma unroll
            for (int c = 0; c < 4; c++) { O2[i][c].x *= corr[i]; O2[i][c].y *= corr[i]; }

        for (int k = 0; k < 128; k += 4) {
            float4 p4[8];
#pragma unroll
            for (int i = 0; i < 8; i++)
                p4[i] = *reinterpret_cast<const float4*>(&Ps[(8 * ti + i) * ST + k]);
#pragma unroll
            for (int c = 0; c < 4; c++) {
                int ca = tn + 16 * (2 * c), cb = tn + 16 * (2 * c + 1);
                float2 v0 = make_float2(Vs[(k + 0) * 128 + ca], Vs[(k + 0) * 128 + cb]);
                float2 v1 = make_float2(Vs[(k + 1) * 128 + ca], Vs[(k + 1) * 128 + cb]);
                float2 v2 = make_float2(Vs[(k + 2) * 128 + ca], Vs[(k + 2) * 128 + cb]);
                float2 v3 = make_float2(Vs[(k + 3) * 128 + ca], Vs[(k + 3) * 128 + cb]);
#pragma unroll
                for (int i = 0; i < 8; i++) {
                    O2[i][c] = ffma2(make_float2(p4[i].x, p4[i].x), v0, O2[i][c]);
                    O2[i][c] = ffma2(make_float2(p4[i].y, p4[i].y), v1, O2[i][c]);
                    O2[i][c] = ffma2(make_float2(p4[i].z, p4[i].z), v2, O2[i][c]);
                    O2[i][c] = ffma2(make_float2(p4[i].w, p4[i].w), v3, O2[i][c]);
                }
            }
        }
    }

#pragma unroll
    for (int i = 0; i < 8; i++) {
        float inv = 1.0f / lrow[i];
        int srow = q0 + 8 * ti + i;
        float* optr = ctx + ((size_t)b * Sq + srow) * (size_t)(NHc * HDc) + h * HDc;
#pragma unroll
        for (int c = 0; c < 4; c++) {
            optr[tn + 16 * (2 * c)]     = O2[i][c].x * inv;
            optr[tn + 16 * (2 * c + 1)] = O2[i][c].y * inv;
        }
    }
}

// ---------------------------------------------------------------------------
extern "C" void kernel_launch(void* const* d_in, const int* in_sizes, int n_in,
                              void* d_out, int out_size)
{
    const float* hidden = (const float*)d_in[0];
    const float* cosp   = (const float*)d_in[1];
    const float* sinp   = (const float*)d_in[2];
    const float* Wq     = (const float*)d_in[3];
    const float* bq     = (const float*)d_in[4];
    const float* Wk     = (const float*)d_in[5];
    const float* bk     = (const float*)d_in[6];
    const float* Wv     = (const float*)d_in[7];
    const float* bv     = (const float*)d_in[8];
    const float* Wo     = (const float*)d_in[9];
    float* out = (float*)d_out;

    float *qb, *kb, *vb, *cb;
    __nv_bfloat16 *ahi, *alo, *bhi, *blo;
    cudaGetSymbolAddress((void**)&qb, g_Q);
    cudaGetSymbolAddress((void**)&kb, g_K);
    cudaGetSymbolAddress((void**)&vb, g_V);
    cudaGetSymbolAddress((void**)&cb, g_ctx);
    cudaGetSymbolAddress((void**)&ahi, g_Ahi);
    cudaGetSymbolAddress((void**)&alo, g_Alo);
    cudaGetSymbolAddress((void**)&bhi, g_Bhi);
    cudaGetSymbolAddress((void**)&blo, g_Blo);

    cudaFuncSetAttribute(gemm_mma<0>, cudaFuncAttributeMaxDynamicSharedMemorySize, GSMEM);
    cudaFuncSetAttribute(gemm_mma<1>, cudaFuncAttributeMaxDynamicSharedMemorySize, GSMEM);
    cudaFuncSetAttribute(flash_kernel, cudaFuncAttributeMaxDynamicSharedMemorySize, FL_SMEM);

    const size_t MK = (size_t)4096 * 4096;
    const size_t HALF = MK / 2;
    dim3 trb(32, 8);

    // gemm_mma<1> (Q proj) stays launch #4 — the launch ncu captures.
    split_kernel<<<HALF / 1024, 256>>>(hidden, ahi, alo, 0, HALF);        // 1
    split_kernel<<<HALF / 1024, 256>>>(hidden, ahi, alo, HALF, HALF);     // 2
    tsplit_kernel<<<dim3(4096 / 32, 4096 / 32), trb>>>(Wq, bhi, blo, 4096);            // 3
    gemm_mma<1><<<dim3(32, 32), 512, GSMEM>>>(ahi, alo, bhi, blo, bq, qb, 4096, NHc);  // 4 <- profiled
    int totQ = Bc * NHc * Sq * 64;
    rope_kernel<<<(totQ + 255) / 256, 256>>>(qb, cosp, sinp, NHc, totQ);               // 5

    tsplit_kernel<<<dim3(1024 / 32, 4096 / 32), trb>>>(Wk, bhi, blo, 1024);
    gemm_mma<1><<<dim3(8, 32), 512, GSMEM>>>(ahi, alo, bhi, blo, bk, kb, 1024, NKVc);
    int totK = Bc * NKVc * Sq * 64;
    rope_kernel<<<(totK + 255) / 256, 256>>>(kb, cosp, sinp, NKVc, totK);

    tsplit_kernel<<<dim3(1024 / 32, 4096 / 32), trb>>>(Wv, bhi, blo, 1024);
    gemm_mma<1><<<dim3(8, 32), 512, GSMEM>>>(ahi, alo, bhi, blo, bv, vb, 1024, NKVc);

    flash_kernel<<<dim3(Sq / 128, NHc, Bc), 256, FL_SMEM>>>(qb, kb, vb, cb);

    split_kernel<<<MK / 1024, 256>>>(cb, ahi, alo, 0, MK);
    tsplit_kernel<<<dim3(4096 / 32, 4096 / 32), trb>>>(Wo, bhi, blo, 4096);
    gemm_mma<0><<<dim3(32, 32), 512, GSMEM>>>(ahi, alo, bhi, blo, nullptr, out, 4096, 0);
}

// round 10
// speedup vs baseline: 1.0194x; 1.0194x over previous
#include <cuda_runtime.h>
#include <cuda_bf16.h>
#include <cstdint>
#include <cstddef>

constexpr int Bc = 2, Sq = 2048, HIDc = 4096, NHc = 32, NKVc = 8, HDc = 128;
constexpr int Kd = 4096;

__device__ float g_Q[(size_t)Bc * NHc * Sq * HDc];
__device__ float g_K[(size_t)Bc * NKVc * Sq * HDc];
__device__ float g_V[(size_t)Bc * NKVc * Sq * HDc];
__device__ float g_ctx[(size_t)Bc * Sq * NHc * HDc];
__device__ __nv_bfloat16 g_Ahi[(size_t)4096 * Kd];
__device__ __nv_bfloat16 g_Alo[(size_t)4096 * Kd];
__device__ __nv_bfloat16 g_Bhi[(size_t)4096 * Kd];
__device__ __nv_bfloat16 g_Blo[(size_t)4096 * Kd];

// ---------------------------------------------------------------------------
__device__ __forceinline__ uint32_t smem_u32(const void* p) {
    uint32_t a;
    asm("{ .reg .u64 t; cvta.to.shared.u64 t, %1; cvt.u32.u64 %0, t; }" : "=r"(a) : "l"(p));
    return a;
}
__device__ __forceinline__ float2 ffma2(float2 a, float2 b, float2 c) {
    unsigned long long ua = *reinterpret_cast<unsigned long long*>(&a);
    unsigned long long ub = *reinterpret_cast<unsigned long long*>(&b);
    unsigned long long uc = *reinterpret_cast<unsigned long long*>(&c);
    unsigned long long ud;
    asm("fma.rn.f32x2 %0, %1, %2, %3;" : "=l"(ud) : "l"(ua), "l"(ub), "l"(uc));
    return *reinterpret_cast<float2*>(&ud);
}
__device__ __forceinline__ void cp16(uint32_t d, const void* g) {
    asm volatile("cp.async.cg.shared.global [%0], [%1], 16;" :: "r"(d), "l"(g));
}
__device__ __forceinline__ void ldm4(uint32_t* r, uint32_t a) {
    asm volatile("ldmatrix.sync.aligned.m8n8.x4.shared.b16 {%0,%1,%2,%3}, [%4];"
        : "=r"(r[0]), "=r"(r[1]), "=r"(r[2]), "=r"(r[3]) : "r"(a));
}
__device__ __forceinline__ void mma16816(float* c, const uint32_t* a, uint32_t b0, uint32_t b1) {
    asm volatile("mma.sync.aligned.m16n8k16.row.col.f32.bf16.bf16.f32 "
        "{%0,%1,%2,%3}, {%4,%5,%6,%7}, {%8,%9}, {%0,%1,%2,%3};"
        : "+f"(c[0]), "+f"(c[1]), "+f"(c[2]), "+f"(c[3])
        : "r"(a[0]), "r"(a[1]), "r"(a[2]), "r"(a[3]), "r"(b0), "r"(b1));
}

// ---------------------------------------------------------------------------
__global__ void split_kernel(const float* __restrict__ x, __nv_bfloat16* __restrict__ hi,
                             __nv_bfloat16* __restrict__ lo, size_t off, size_t cnt)
{
    size_t i = off + ((size_t)blockIdx.x * blockDim.x + threadIdx.x) * 4;
    if (i >= off + cnt) return;
    float4 v = *reinterpret_cast<const float4*>(x + i);
    __nv_bfloat16 h0 = __float2bfloat16(v.x), h1 = __float2bfloat16(v.y);
    __nv_bfloat16 h2 = __float2bfloat16(v.z), h3 = __float2bfloat16(v.w);
    *reinterpret_cast<__nv_bfloat162*>(hi + i)     = {h0, h1};
    *reinterpret_cast<__nv_bfloat162*>(hi + i + 2) = {h2, h3};
    *reinterpret_cast<__nv_bfloat162*>(lo + i) =
        {__float2bfloat16(v.x - __bfloat162float(h0)),
         __float2bfloat16(v.y - __bfloat162float(h1))};
    *reinterpret_cast<__nv_bfloat162*>(lo + i + 2) =
        {__float2bfloat16(v.z - __bfloat162float(h2)),
         __float2bfloat16(v.w - __bfloat162float(h3))};
}

// ---------------------------------------------------------------------------
// Transpose+split W[4096,N] fp32 -> Thi/Tlo [N,4096] bf16, row offset ro.
// ---------------------------------------------------------------------------
__global__ void tsplit_kernel(const float* __restrict__ W, __nv_bfloat16* __restrict__ Thi,
                              __nv_bfloat16* __restrict__ Tlo, int N, int ro)
{
    __shared__ float t[32][33];
    int n0 = blockIdx.x * 32, k0 = blockIdx.y * 32;
    int tx = threadIdx.x, ty = threadIdx.y;
#pragma unroll
    for (int j = 0; j < 4; j++)
        t[ty + 8 * j][tx] = W[(size_t)(k0 + ty + 8 * j) * N + n0 + tx];
    __syncthreads();
#pragma unroll
    for (int j = 0; j < 4; j++) {
        float v = t[tx][ty + 8 * j];
        __nv_bfloat16 h = __float2bfloat16(v);
        size_t idx = (size_t)(ro + n0 + ty + 8 * j) * Kd + k0 + tx;
        Thi[idx] = h;
        Tlo[idx] = __float2bfloat16(v - __bfloat162float(h));
    }
}

// ---------------------------------------------------------------------------
// bf16 mma.sync GEMM over virtual K' = 3*4096 (AhiBhi, AloBhi, AhiBlo).
// R8 geometry (256 thr, 8 warps, warp tile 32x64, 2 CTAs/SM) + chunk-PAIRED
// barriers: one wait+sync per TWO chunks (64 MMAs), 5 SMEM stages.
// MODE 0: row-major C, no bias. MODE 1: bias + (B,heads,S,HD) store.
// MODE 2: fused KV — cols <1024 -> C(K layout), >=1024 -> C2(V layout).
// ---------------------------------------------------------------------------
constexpr int GSTAGE = 20480;
constexpr int GNSTG  = 5;
constexpr int GSMEM  = GNSTG * GSTAGE;  // 102400 (×2 CTAs = 200 KB/SM)

template <int MODE>
__global__ __launch_bounds__(256, 2)
void gemm_mma(const __nv_bfloat16* __restrict__ Ahi, const __nv_bfloat16* __restrict__ Alo,
              const __nv_bfloat16* __restrict__ Bhi, const __nv_bfloat16* __restrict__ Blo,
              const float* __restrict__ bias, const float* __restrict__ bias2,
              float* __restrict__ C, float* __restrict__ C2, int N, int heads)
{
    extern __shared__ __align__(16) char smc[];
    const uint32_t sbase = smem_u32(smc);
    const int tid = threadIdx.x;
    const int warp = tid >> 5, lane = tid & 31;
    const int m0 = blockIdx.y * 128, n0 = blockIdx.x * 128;
    constexpr int NKI = 3 * (Kd / 32);   // 384 chunks
    constexpr int NPAIR = NKI / 2;       // 192 pairs

    auto issue = [&](int kc) {
        const int buf = kc % GNSTG;
        const uint32_t sb = sbase + buf * GSTAGE;
        const int seg = kc >> 7;
        const int k0 = (kc & 127) * 32;
        const __nv_bfloat16* Aseg = (seg == 1) ? Alo : Ahi;
        const __nv_bfloat16* Bseg = (seg == 2) ? Blo : Bhi;
#pragma unroll
        for (int j = 0; j < 4; j++) {
            int task = tid + j * 256;
            if (task < 512) {
                int row = task >> 2, ch = task & 3;
                cp16(sb + row * 80 + ch * 16,
                     Aseg + (size_t)(m0 + row) * Kd + k0 + ch * 8);
            } else {
                int t2 = task - 512;
                int row = t2 >> 2, ch = t2 & 3;
                cp16(sb + 10240 + row * 80 + ch * 16,
                     Bseg + (size_t)(n0 + row) * Kd + k0 + ch * 8);
            }
        }
        asm volatile("cp.async.commit_group;" ::: "memory");
    };

    const int wm = (warp >> 1) * 32, wn = (warp & 1) * 64;

    uint32_t fa[2][2][4];
    uint32_t fb[2][4][4];

    auto ldfrags = [&](int kc) {
        const uint32_t sA = sbase + (kc % GNSTG) * GSTAGE;
        const uint32_t sB = sA + 10240;
#pragma unroll
        for (int ks = 0; ks < 2; ks++) {
            const int kb = ks * 32;
#pragma unroll
            for (int mi = 0; mi < 2; mi++)
                ldm4(fa[ks][mi], sA + (wm + mi * 16 + (lane & 15)) * 80 + kb + (lane >> 4) * 16);
#pragma unroll
            for (int nb = 0; nb < 4; nb++)
                ldm4(fb[ks][nb], sB + (wn + nb * 16 + ((lane >> 4) << 3) + (lane & 7)) * 80
                                   + kb + ((lane >> 3) & 1) * 16);
        }
    };

    float acc[2][8][4];
#pragma unroll
    for (int mi = 0; mi < 2; mi++)
#pragma unroll
        for (int ni = 0; ni < 8; ni++)
#pragma unroll
            for (int r = 0; r < 4; r++) acc[mi][ni][r] = 0.f;

    auto mmablock = [&]() {
#pragma unroll
        for (int ks = 0; ks < 2; ks++)
#pragma unroll
            for (int mi = 0; mi < 2; mi++)
#pragma unroll
                for (int ni = 0; ni < 8; ni++)
                    mma16816(acc[mi][ni], fa[ks][mi],
                             fb[ks][ni >> 1][2 * (ni & 1)], fb[ks][ni >> 1][2 * (ni & 1) + 1]);
    };

    // Prologue: fill 5 stages, arm chunk 0 frags.
    issue(0); issue(1); issue(2); issue(3); issue(4);
    asm volatile("cp.async.wait_group 3;" ::: "memory");  // chunks 0,1 complete
    __syncthreads();
    ldfrags(0);

    for (int p = 0; p < NPAIR; p++) {
        mmablock();            // chunk 2p
        ldfrags(2 * p + 1);    // chunk 2p+1 (completed & published at last barrier)
        mmablock();            // chunk 2p+1
        if (p + 1 < NPAIR) {
            // complete through chunk 2p+3 (covers next pair's both ldfrags)
            asm volatile("cp.async.wait_group 1;" ::: "memory");
            __syncthreads();   // publish 2p+2, 2p+3; buffers 2p,2p+1 free
            ldfrags(2 * p + 2);
            if (2 * p + 5 < NKI) issue(2 * p + 5);
            if (2 * p + 6 < NKI) issue(2 * p + 6);
        }
    }

    // Epilogue
#pragma unroll
    for (int mi = 0; mi < 2; mi++) {
#pragma unroll
        for (int rg = 0; rg < 2; rg++) {
            const int m = m0 + wm + mi * 16 + rg * 8 + (lane >> 2);
            const int bidx = m >> 11, sidx = m & 2047;
#pragma unroll
            for (int ni = 0; ni < 8; ni++) {
                const int col = n0 + wn + ni * 8 + (lane & 3) * 2;
                float v0 = acc[mi][ni][rg * 2 + 0];
                float v1 = acc[mi][ni][rg * 2 + 1];
                float* dst;
                if (MODE == 0) {
                    dst = C + (size_t)m * N + col;
                } else if (MODE == 1) {
                    v0 += __ldg(bias + col);
                    v1 += __ldg(bias + col + 1);
                    int h = col >> 7, d = col & 127;
                    dst = C + (((size_t)bidx * heads + h) * Sq + sidx) * HDc + d;
                } else {
                    // fused KV: cols <1024 -> K (C, bias), >=1024 -> V (C2, bias2)
                    int c2 = col & 1023;
                    const float* bs = (col < 1024) ? bias : bias2;
                    float* base = (col < 1024) ? C : C2;
                    v0 += __ldg(bs + c2);
                    v1 += __ldg(bs + c2 + 1);
                    int h = c2 >> 7, d = c2 & 127;
                    dst = base + (((size_t)bidx * NKVc + h) * Sq + sidx) * HDc + d;
                }
                *reinterpret_cast<float2*>(dst) = make_float2(v0, v1);
            }
        }
    }
}

// ---------------------------------------------------------------------------
__global__ void rope_kernel(float* __restrict__ x, const float* __restrict__ cosp,
                            const float* __restrict__ sinp, int heads, int total)
{
    int i = blockIdx.x * blockDim.x + threadIdx.x;
    if (i >= total) return;
    int dd = i & 63;
    int s = (i >> 6) & 2047;
    int bh = i >> 17;
    int h = bh % heads, b = bh / heads;
    size_t base = (((size_t)b * heads + h) * Sq + s) * HDc;
    size_t cbase = ((size_t)b * Sq + s) * HDc;
    float x1 = x[base + dd], x2 = x[base + dd + 64];
    float c1 = cosp[cbase + dd], c2 = cosp[cbase + dd + 64];
    float s1 = sinp[cbase + dd], s2 = sinp[cbase + dd + 64];
    x[base + dd]      = x1 * c1 - x2 * s1;
    x[base + dd + 64] = x2 * c2 + x1 * s2;
}

// ---------------------------------------------------------------------------
constexpr int FL_SMEM = (128 * 132 * 2 + 128 * 128) * 4;

__global__ __launch_bounds__(256, 1)
void flash_kernel(const float* __restrict__ Q, const float* __restrict__ Kg,
                  const float* __restrict__ Vg, float* __restrict__ ctx)
{
    constexpr int ST = 132;
    extern __shared__ __align__(16) float sm[];
    float* Qs = sm;
    float* Ks = sm + 128 * ST;
    float* Ps = Ks;
    float* Vs = sm + 2 * 128 * ST;

    const int tid = threadIdx.x;
    const int ti = tid >> 4, tn = tid & 15;
    const int b = blockIdx.z, h = blockIdx.y;
    const int kvh = h >> 2;
    const int q0 = blockIdx.x * 128;

    const float* qptr = Q  + (((size_t)b * NHc  + h)   * Sq + q0) * (size_t)HDc;
    const float* kptr = Kg + (((size_t)b * NKVc + kvh) * Sq) * (size_t)HDc;
    const float* vptr = Vg + (((size_t)b * NKVc + kvh) * Sq) * (size_t)HDc;

#pragma unroll
    for (int i = 0; i < 16; i++) {
        int idx = tid + i * 256;
        int r = idx >> 5, c = (idx & 31) * 4;
        float4 q4 = *reinterpret_cast<const float4*>(qptr + (size_t)r * HDc + c);
        Qs[r * ST + c] = q4.x; Qs[r * ST + c + 1] = q4.y;
        Qs[r * ST + c + 2] = q4.z; Qs[r * ST + c + 3] = q4.w;
    }

    float2 O2[8][4];
    float mrow[8], lrow[8];
#pragma unroll
    for (int i = 0; i < 8; i++) {
        mrow[i] = -1e30f; lrow[i] = 0.f;
#pragma unroll
        for (int c = 0; c < 4; c++) O2[i][c] = make_float2(0.f, 0.f);
    }

    const float scale = 0.08838834764831845f;

    for (int n0 = 0; n0 < Sq; n0 += 128) {
        __syncthreads();
#pragma unroll
        for (int i = 0; i < 16; i++) {
            int idx = tid + i * 256;
            int r = idx >> 5, c = (idx & 31) * 4;
            float4 k4 = *reinterpret_cast<const float4*>(kptr + (size_t)(n0 + r) * HDc + c);
            Ks[r * ST + c] = k4.x; Ks[r * ST + c + 1] = k4.y;
            Ks[r * ST + c + 2] = k4.z; Ks[r * ST + c + 3] = k4.w;
            *reinterpret_cast<float4*>(Vs + r * 128 + c) =
                *reinterpret_cast<const float4*>(vptr + (size_t)(n0 + r) * HDc + c);
        }
        __syncthreads();

        float2 s2[8][4];
#pragma unroll
        for (int i = 0; i < 8; i++)
#pragma unroll
            for (int c = 0; c < 4; c++) s2[i][c] = make_float2(0.f, 0.f);

        for (int d = 0; d < HDc; d += 4) {
            float4 q4[8];
#pragma unroll
            for (int i = 0; i < 8; i++)
                q4[i] = *reinterpret_cast<const float4*>(&Qs[(8 * ti + i) * ST + d]);
#pragma unroll
            for (int c = 0; c < 4; c++) {
                float4 ka = *reinterpret_cast<const float4*>(&Ks[(tn + 16 * (2 * c)) * ST + d]);
                float4 kb = *reinterpret_cast<const float4*>(&Ks[(tn + 16 * (2 * c + 1)) * ST + d]);
#pragma unroll
                for (int i = 0; i < 8; i++) {
                    s2[i][c] = ffma2(make_float2(q4[i].x, q4[i].x), make_float2(ka.x, kb.x), s2[i][c]);
                    s2[i][c] = ffma2(make_float2(q4[i].y, q4[i].y), make_float2(ka.y, kb.y), s2[i][c]);
                    s2[i][c] = ffma2(make_float2(q4[i].z, q4[i].z), make_float2(ka.z, kb.z), s2[i][c]);
                    s2[i][c] = ffma2(make_float2(q4[i].w, q4[i].w), make_float2(ka.w, kb.w), s2[i][c]);
                }
            }
        }

        float corr[8];
#pragma unroll
        for (int i = 0; i < 8; i++) {
            float mt = fmaxf(fmaxf(fmaxf(s2[i][0].x, s2[i][0].y), fmaxf(s2[i][1].x, s2[i][1].y)),
                             fmaxf(fmaxf(s2[i][2].x, s2[i][2].y), fmaxf(s2[i][3].x, s2[i][3].y)));
            mt *= scale;
#pragma unroll
            for (int off = 1; off < 16; off <<= 1)
                mt = fmaxf(mt, __shfl_xor_sync(0xffffffffu, mt, off));
            float mnew = fmaxf(mrow[i], mt);
            corr[i] = __expf(mrow[i] - mnew);
            mrow[i] = mnew;
        }
#pragma unroll
        for (int i = 0; i < 8; i++) {
            float sum = 0.f;
#pragma unroll
            for (int c = 0; c < 4; c++) {
                float px = __expf(s2[i][c].x * scale - mrow[i]);
                float py = __expf(s2[i][c].y * scale - mrow[i]);
                s2[i][c].x = px; s2[i][c].y = py;
                sum += px + py;
            }
#pragma unroll
            for (int off = 1; off < 16; off <<= 1)
                sum += __shfl_xor_sync(0xffffffffu, sum, off);
            lrow[i] = lrow[i] * corr[i] + sum;
        }

        __syncthreads();

#pragma unroll
        for (int i = 0; i < 8; i++) {
            int r = 8 * ti + i;
#pragma unroll
            for (int c = 0; c < 4; c++) {
                Ps[r * ST + tn + 16 * (2 * c)]     = s2[i][c].x;
                Ps[r * ST + tn + 16 * (2 * c + 1)] = s2[i][c].y;
            }
        }
        __syncwarp();

#pragma unroll
        for (int i = 0; i < 8; i++)
#pragma unroll
            for (int c = 0; c < 4; c++) { O2[i][c].x *= corr[i]; O2[i][c].y *= corr[i]; }

        for (int k = 0; k < 128; k += 4) {
            float4 p4[8];
#pragma unroll
            for (int i = 0; i < 8; i++)
                p4[i] = *reinterpret_cast<const float4*>(&Ps[(8 * ti + i) * ST + k]);
#pragma unroll
            for (int c = 0; c < 4; c++) {
                int ca = tn + 16 * (2 * c), cb = tn + 16 * (2 * c + 1);
                float2 v0 = make_float2(Vs[(k + 0) * 128 + ca], Vs[(k + 0) * 128 + cb]);
                float2 v1 = make_float2(Vs[(k + 1) * 128 + ca], Vs[(k + 1) * 128 + cb]);
                float2 v2 = make_float2(Vs[(k + 2) * 128 + ca], Vs[(k + 2) * 128 + cb]);
                float2 v3 = make_float2(Vs[(k + 3) * 128 + ca], Vs[(k + 3) * 128 + cb]);
#pragma unroll
                for (int i = 0; i < 8; i++) {
                    O2[i][c] = ffma2(make_float2(p4[i].x, p4[i].x), v0, O2[i][c]);
                    O2[i][c] = ffma2(make_float2(p4[i].y, p4[i].y), v1, O2[i][c]);
                    O2[i][c] = ffma2(make_float2(p4[i].z, p4[i].z), v2, O2[i][c]);
                    O2[i][c] = ffma2(make_float2(p4[i].w, p4[i].w), v3, O2[i][c]);
                }
            }
        }
    }

#pragma unroll
    for (int i = 0; i < 8; i++) {
        float inv = 1.0f / lrow[i];
        int srow = q0 + 8 * ti + i;
        float* optr = ctx + ((size_t)b * Sq + srow) * (size_t)(NHc * HDc) + h * HDc;
#pragma unroll
        for (int c = 0; c < 4; c++) {
            optr[tn + 16 * (2 * c)]     = O2[i][c].x * inv;
            optr[tn + 16 * (2 * c + 1)] = O2[i][c].y * inv;
        }
    }
}

// ---------------------------------------------------------------------------
extern "C" void kernel_launch(void* const* d_in, const int* in_sizes, int n_in,
                              void* d_out, int out_size)
{
    const float* hidden = (const float*)d_in[0];
    const float* cosp   = (const float*)d_in[1];
    const float* sinp   = (const float*)d_in[2];
    const float* Wq     = (const float*)d_in[3];
    const float* bq     = (const float*)d_in[4];
    const float* Wk     = (const float*)d_in[5];
    const float* bk     = (const float*)d_in[6];
    const float* Wv     = (const float*)d_in[7];
    const float* bv     = (const float*)d_in[8];
    const float* Wo     = (const float*)d_in[9];
    float* out = (float*)d_out;

    float *qb, *kb, *vb, *cb;
    __nv_bfloat16 *ahi, *alo, *bhi, *blo;
    cudaGetSymbolAddress((void**)&qb, g_Q);
    cudaGetSymbolAddress((void**)&kb, g_K);
    cudaGetSymbolAddress((void**)&vb, g_V);
    cudaGetSymbolAddress((void**)&cb, g_ctx);
    cudaGetSymbolAddress((void**)&ahi, g_Ahi);
    cudaGetSymbolAddress((void**)&alo, g_Alo);
    cudaGetSymbolAddress((void**)&bhi, g_Bhi);
    cudaGetSymbolAddress((void**)&blo, g_Blo);

    cudaFuncSetAttribute(gemm_mma<0>, cudaFuncAttributeMaxDynamicSharedMemorySize, GSMEM);
    cudaFuncSetAttribute(gemm_mma<1>, cudaFuncAttributeMaxDynamicSharedMemorySize, GSMEM);
    cudaFuncSetAttribute(gemm_mma<2>, cudaFuncAttributeMaxDynamicSharedMemorySize, GSMEM);
    cudaFuncSetAttribute(flash_kernel, cudaFuncAttributeMaxDynamicSharedMemorySize, FL_SMEM);

    const size_t MK = (size_t)4096 * 4096;
    const size_t HALF = MK / 2;
    dim3 trb(32, 8);

    // gemm_mma<1> (Q proj) stays launch #4 — the launch ncu captures.
    split_kernel<<<HALF / 1024, 256>>>(hidden, ahi, alo, 0, HALF);                       // 1
    split_kernel<<<HALF / 1024, 256>>>(hidden, ahi, alo, HALF, HALF);                    // 2
    tsplit_kernel<<<dim3(128, 128), trb>>>(Wq, bhi, blo, 4096, 0);                       // 3
    gemm_mma<1><<<dim3(32, 32), 256, GSMEM>>>(ahi, alo, bhi, blo, bq, nullptr,
                                              qb, nullptr, 4096, NHc);                   // 4 <- profiled
    int totQ = Bc * NHc * Sq * 64;
    rope_kernel<<<(totQ + 255) / 256, 256>>>(qb, cosp, sinp, NHc, totQ);                 // 5

    // Fused K+V projection: B' rows [0,1024) = Wk^T, [1024,2048) = Wv^T
    tsplit_kernel<<<dim3(32, 128), trb>>>(Wk, bhi, blo, 1024, 0);
    tsplit_kernel<<<dim3(32, 128), trb>>>(Wv, bhi, blo, 1024, 1024);
    gemm_mma<2><<<dim3(16, 32), 256, GSMEM>>>(ahi, alo, bhi, blo, bk, bv,
                                              kb, vb, 2048, NKVc);
    int totK = Bc * NKVc * Sq * 64;
    rope_kernel<<<(totK + 255) / 256, 256>>>(kb, cosp, sinp, NKVc, totK);

    flash_kernel<<<dim3(Sq / 128, NHc, Bc), 256, FL_SMEM>>>(qb, kb, vb, cb);

    split_kernel<<<MK / 1024, 256>>>(cb, ahi, alo, 0, MK);
    tsplit_kernel<<<dim3(128, 128), trb>>>(Wo, bhi, blo, 4096, 0);
    gemm_mma<0><<<dim3(32, 32), 256, GSMEM>>>(ahi, alo, bhi, blo, nullptr, nullptr,
                                              out, nullptr, 4096, 0);
}

// round 11
// speedup vs baseline: 1.1029x; 1.0819x over previous
#include <cuda_runtime.h>
#include <cuda_bf16.h>
#include <cstdint>
#include <cstddef>

constexpr int Bc = 2, Sq = 2048, HIDc = 4096, NHc = 32, NKVc = 8, HDc = 128;
constexpr int Kd = 4096;
constexpr int NQKV = 6144;  // fused projection width: 4096 Q + 1024 K + 1024 V

__device__ float g_Q[(size_t)Bc * NHc * Sq * HDc];
__device__ float g_K[(size_t)Bc * NKVc * Sq * HDc];
__device__ float g_V[(size_t)Bc * NKVc * Sq * HDc];
__device__ float g_ctx[(size_t)Bc * Sq * NHc * HDc];
__device__ __nv_bfloat16 g_Ahi[(size_t)4096 * Kd];
__device__ __nv_bfloat16 g_Alo[(size_t)4096 * Kd];
__device__ __nv_bfloat16 g_Bhi[(size_t)NQKV * Kd];
__device__ __nv_bfloat16 g_Blo[(size_t)NQKV * Kd];

// ---------------------------------------------------------------------------
__device__ __forceinline__ uint32_t smem_u32(const void* p) {
    uint32_t a;
    asm("{ .reg .u64 t; cvta.to.shared.u64 t, %1; cvt.u32.u64 %0, t; }" : "=r"(a) : "l"(p));
    return a;
}
__device__ __forceinline__ float2 ffma2(float2 a, float2 b, float2 c) {
    unsigned long long ua = *reinterpret_cast<unsigned long long*>(&a);
    unsigned long long ub = *reinterpret_cast<unsigned long long*>(&b);
    unsigned long long uc = *reinterpret_cast<unsigned long long*>(&c);
    unsigned long long ud;
    asm("fma.rn.f32x2 %0, %1, %2, %3;" : "=l"(ud) : "l"(ua), "l"(ub), "l"(uc));
    return *reinterpret_cast<float2*>(&ud);
}
__device__ __forceinline__ void cp16(uint32_t d, const void* g) {
    asm volatile("cp.async.cg.shared.global [%0], [%1], 16;" :: "r"(d), "l"(g));
}
__device__ __forceinline__ void ldm4(uint32_t* r, uint32_t a) {
    asm volatile("ldmatrix.sync.aligned.m8n8.x4.shared.b16 {%0,%1,%2,%3}, [%4];"
        : "=r"(r[0]), "=r"(r[1]), "=r"(r[2]), "=r"(r[3]) : "r"(a));
}
__device__ __forceinline__ void mma16816(float* c, const uint32_t* a, uint32_t b0, uint32_t b1) {
    asm volatile("mma.sync.aligned.m16n8k16.row.col.f32.bf16.bf16.f32 "
        "{%0,%1,%2,%3}, {%4,%5,%6,%7}, {%8,%9}, {%0,%1,%2,%3};"
        : "+f"(c[0]), "+f"(c[1]), "+f"(c[2]), "+f"(c[3])
        : "r"(a[0]), "r"(a[1]), "r"(a[2]), "r"(a[3]), "r"(b0), "r"(b1));
}

// ---------------------------------------------------------------------------
// Device-side helpers for split / transpose-split work items
// ---------------------------------------------------------------------------
__device__ __forceinline__ void split_block(const float* __restrict__ x,
                                            __nv_bfloat16* __restrict__ hi,
                                            __nv_bfloat16* __restrict__ lo,
                                            size_t blk)
{
    size_t i = blk * 1024 + (size_t)threadIdx.x * 4;
    float4 v = *reinterpret_cast<const float4*>(x + i);
    __nv_bfloat16 h0 = __float2bfloat16(v.x), h1 = __float2bfloat16(v.y);
    __nv_bfloat16 h2 = __float2bfloat16(v.z), h3 = __float2bfloat16(v.w);
    *reinterpret_cast<__nv_bfloat162*>(hi + i)     = {h0, h1};
    *reinterpret_cast<__nv_bfloat162*>(hi + i + 2) = {h2, h3};
    *reinterpret_cast<__nv_bfloat162*>(lo + i) =
        {__float2bfloat16(v.x - __bfloat162float(h0)),
         __float2bfloat16(v.y - __bfloat162float(h1))};
    *reinterpret_cast<__nv_bfloat162*>(lo + i + 2) =
        {__float2bfloat16(v.z - __bfloat162float(h2)),
         __float2bfloat16(v.w - __bfloat162float(h3))};
}

__device__ __forceinline__ void tsplit_block(const float* __restrict__ W,
                                             __nv_bfloat16* __restrict__ Thi,
                                             __nv_bfloat16* __restrict__ Tlo,
                                             int N, int ro, int tile)
{
    __shared__ float t[32][33];
    int nt = N / 32;
    int n0 = (tile % nt) * 32, k0 = (tile / nt) * 32;
    int tx = threadIdx.x & 31, ty = threadIdx.x >> 5;
#pragma unroll
    for (int j = 0; j < 4; j++)
        t[ty + 8 * j][tx] = W[(size_t)(k0 + ty + 8 * j) * N + n0 + tx];
    __syncthreads();
#pragma unroll
    for (int j = 0; j < 4; j++) {
        float v = t[tx][ty + 8 * j];
        __nv_bfloat16 h = __float2bfloat16(v);
        size_t idx = (size_t)(ro + n0 + ty + 8 * j) * Kd + k0 + tx;
        Thi[idx] = h;
        Tlo[idx] = __float2bfloat16(v - __bfloat162float(h));
    }
}

// Fused prep: blocks [0,16384) split hidden; then transpose-split Wq/Wk/Wv.
__global__ void prep_kernel(const float* __restrict__ hidden,
                            __nv_bfloat16* __restrict__ ahi, __nv_bfloat16* __restrict__ alo,
                            const float* __restrict__ Wq, const float* __restrict__ Wk,
                            const float* __restrict__ Wv,
                            __nv_bfloat16* __restrict__ bhi, __nv_bfloat16* __restrict__ blo)
{
    int b = blockIdx.x;
    if (b < 16384) { split_block(hidden, ahi, alo, b); return; }
    int tb = b - 16384;
    if (tb < 16384)      tsplit_block(Wq, bhi, blo, 4096, 0,    tb);
    else if (tb < 20480) tsplit_block(Wk, bhi, blo, 1024, 4096, tb - 16384);
    else                 tsplit_block(Wv, bhi, blo, 1024, 5120, tb - 20480);
}

// Standalone split (for ctx) and transpose-split (for Wo), flat 256 threads.
__global__ void split_kernel(const float* __restrict__ x, __nv_bfloat16* __restrict__ hi,
                             __nv_bfloat16* __restrict__ lo)
{
    split_block(x, hi, lo, blockIdx.x);
}
__global__ void tsplit_kernel(const float* __restrict__ W, __nv_bfloat16* __restrict__ Thi,
                              __nv_bfloat16* __restrict__ Tlo)
{
    tsplit_block(W, Thi, Tlo, 4096, 0, blockIdx.x);
}

// ---------------------------------------------------------------------------
// bf16 mma.sync GEMM over virtual K' = 3*4096 — EXACT R8 mainloop (best).
// MODE 0: row-major C (N=4096), no bias.
// MODE 1: fused QKV epilogue (N=6144): col<4096 -> Q, <5120 -> K, else V.
// ---------------------------------------------------------------------------
constexpr int GSTAGE = 20480;
constexpr int GNSTG  = 4;
constexpr int GSMEM  = GNSTG * GSTAGE;  // 81920

template <int MODE>
__global__ __launch_bounds__(256, 2)
void gemm_mma(const __nv_bfloat16* __restrict__ Ahi, const __nv_bfloat16* __restrict__ Alo,
              const __nv_bfloat16* __restrict__ Bhi, const __nv_bfloat16* __restrict__ Blo,
              const float* __restrict__ bq, const float* __restrict__ bk,
              const float* __restrict__ bv,
              float* __restrict__ Cq, float* __restrict__ Ck, float* __restrict__ Cv,
              int N)
{
    extern __shared__ __align__(16) char smc[];
    const uint32_t sbase = smem_u32(smc);
    const int tid = threadIdx.x;
    const int warp = tid >> 5, lane = tid & 31;
    const int m0 = blockIdx.y * 128, n0 = blockIdx.x * 128;
    constexpr int NKI = 3 * (Kd / 32);

    auto issue = [&](int kc) {
        const int buf = kc % GNSTG;
        const uint32_t sb = sbase + buf * GSTAGE;
        const int seg = kc >> 7;
        const int k0 = (kc & 127) * 32;
        const __nv_bfloat16* Aseg = (seg == 1) ? Alo : Ahi;
        const __nv_bfloat16* Bseg = (seg == 2) ? Blo : Bhi;
#pragma unroll
        for (int j = 0; j < 4; j++) {
            int task = tid + j * 256;
            if (task < 512) {
                int row = task >> 2, ch = task & 3;
                cp16(sb + row * 80 + ch * 16,
                     Aseg + (size_t)(m0 + row) * Kd + k0 + ch * 8);
            } else {
                int t2 = task - 512;
                int row = t2 >> 2, ch = t2 & 3;
                cp16(sb + 10240 + row * 80 + ch * 16,
                     Bseg + (size_t)(n0 + row) * Kd + k0 + ch * 8);
            }
        }
        asm volatile("cp.async.commit_group;" ::: "memory");
    };

    const int wm = (warp >> 1) * 32, wn = (warp & 1) * 64;

    uint32_t fa[2][2][4];
    uint32_t fb[2][4][4];

    auto ldfrags = [&](int buf) {
        const uint32_t sA = sbase + buf * GSTAGE;
        const uint32_t sB = sA + 10240;
#pragma unroll
        for (int ks = 0; ks < 2; ks++) {
            const int kb = ks * 32;
#pragma unroll
            for (int mi = 0; mi < 2; mi++)
                ldm4(fa[ks][mi], sA + (wm + mi * 16 + (lane & 15)) * 80 + kb + (lane >> 4) * 16);
#pragma unroll
            for (int nb = 0; nb < 4; nb++)
                ldm4(fb[ks][nb], sB + (wn + nb * 16 + ((lane >> 4) << 3) + (lane & 7)) * 80
                                   + kb + ((lane >> 3) & 1) * 16);
        }
    };

    float acc[2][8][4];
#pragma unroll
    for (int mi = 0; mi < 2; mi++)
#pragma unroll
        for (int ni = 0; ni < 8; ni++)
#pragma unroll
            for (int r = 0; r < 4; r++) acc[mi][ni][r] = 0.f;

    issue(0);
    issue(1);
    issue(2);
    asm volatile("cp.async.wait_group 2;" ::: "memory");
    __syncthreads();
    ldfrags(0);
    issue(3);

    for (int kc = 0; kc < NKI; kc++) {
#pragma unroll
        for (int ks = 0; ks < 2; ks++)
#pragma unroll
            for (int mi = 0; mi < 2; mi++)
#pragma unroll
                for (int ni = 0; ni < 8; ni++)
                    mma16816(acc[mi][ni], fa[ks][mi],
                             fb[ks][ni >> 1][2 * (ni & 1)], fb[ks][ni >> 1][2 * (ni & 1) + 1]);

        if (kc + 1 < NKI) {
            asm volatile("cp.async.wait_group 2;" ::: "memory");
            __syncthreads();
            ldfrags((kc + 1) % GNSTG);
            if (kc + 4 < NKI) issue(kc + 4);
        }
    }

    // Epilogue
#pragma unroll
    for (int mi = 0; mi < 2; mi++) {
#pragma unroll
        for (int rg = 0; rg < 2; rg++) {
            const int m = m0 + wm + mi * 16 + rg * 8 + (lane >> 2);
            const int bidx = m >> 11, sidx = m & 2047;
#pragma unroll
            for (int ni = 0; ni < 8; ni++) {
                const int col = n0 + wn + ni * 8 + (lane & 3) * 2;
                float v0 = acc[mi][ni][rg * 2 + 0];
                float v1 = acc[mi][ni][rg * 2 + 1];
                float* dst;
                if (MODE == 0) {
                    dst = Cq + (size_t)m * N + col;
                } else {
                    // fused QKV routing (block-uniform: n0 aligned to 128)
                    const float* bs;
                    float* base;
                    int c2, heads;
                    if (col < 4096)      { bs = bq; base = Cq; c2 = col;        heads = NHc; }
                    else if (col < 5120) { bs = bk; base = Ck; c2 = col - 4096; heads = NKVc; }
                    else                 { bs = bv; base = Cv; c2 = col - 5120; heads = NKVc; }
                    v0 += __ldg(bs + c2);
                    v1 += __ldg(bs + c2 + 1);
                    int h = c2 >> 7, d = c2 & 127;
                    dst = base + (((size_t)bidx * heads + h) * Sq + sidx) * HDc + d;
                }
                *reinterpret_cast<float2*>(dst) = make_float2(v0, v1);
            }
        }
    }
}

// ---------------------------------------------------------------------------
// Fused RoPE for Q and K in one launch.
// ---------------------------------------------------------------------------
__global__ void rope2_kernel(float* __restrict__ q, float* __restrict__ k,
                             const float* __restrict__ cosp, const float* __restrict__ sinp)
{
    const int totQ = Bc * NHc * Sq * 64;
    const int totK = Bc * NKVc * Sq * 64;
    int i = blockIdx.x * blockDim.x + threadIdx.x;
    if (i >= totQ + totK) return;
    float* x;
    int heads;
    if (i < totQ) { x = q; heads = NHc; }
    else          { x = k; heads = NKVc; i -= totQ; }
    int dd = i & 63;
    int s = (i >> 6) & 2047;
    int bh = i >> 17;
    int h = bh % heads, b = bh / heads;
    size_t base = (((size_t)b * heads + h) * Sq + s) * HDc;
    size_t cbase = ((size_t)b * Sq + s) * HDc;
    float x1 = x[base + dd], x2 = x[base + dd + 64];
    float c1 = cosp[cbase + dd], c2 = cosp[cbase + dd + 64];
    float s1 = sinp[cbase + dd], s2 = sinp[cbase + dd + 64];
    x[base + dd]      = x1 * c1 - x2 * s1;
    x[base + dd + 64] = x2 * c2 + x1 * s2;
}

// ---------------------------------------------------------------------------
// Flash attention fp32 (unchanged, best). grid (Sq/128, NH, B), 256 threads.
// ---------------------------------------------------------------------------
constexpr int FL_SMEM = (128 * 132 * 2 + 128 * 128) * 4;

__global__ __launch_bounds__(256, 1)
void flash_kernel(const float* __restrict__ Q, const float* __restrict__ Kg,
                  const float* __restrict__ Vg, float* __restrict__ ctx)
{
    constexpr int ST = 132;
    extern __shared__ __align__(16) float sm[];
    float* Qs = sm;
    float* Ks = sm + 128 * ST;
    float* Ps = Ks;
    float* Vs = sm + 2 * 128 * ST;

    const int tid = threadIdx.x;
    const int ti = tid >> 4, tn = tid & 15;
    const int b = blockIdx.z, h = blockIdx.y;
    const int kvh = h >> 2;
    const int q0 = blockIdx.x * 128;

    const float* qptr = Q  + (((size_t)b * NHc  + h)   * Sq + q0) * (size_t)HDc;
    const float* kptr = Kg + (((size_t)b * NKVc + kvh) * Sq) * (size_t)HDc;
    const float* vptr = Vg + (((size_t)b * NKVc + kvh) * Sq) * (size_t)HDc;

#pragma unroll
    for (int i = 0; i < 16; i++) {
        int idx = tid + i * 256;
        int r = idx >> 5, c = (idx & 31) * 4;
        float4 q4 = *reinterpret_cast<const float4*>(qptr + (size_t)r * HDc + c);
        Qs[r * ST + c] = q4.x; Qs[r * ST + c + 1] = q4.y;
        Qs[r * ST + c + 2] = q4.z; Qs[r * ST + c + 3] = q4.w;
    }

    float2 O2[8][4];
    float mrow[8], lrow[8];
#pragma unroll
    for (int i = 0; i < 8; i++) {
        mrow[i] = -1e30f; lrow[i] = 0.f;
#pragma unroll
        for (int c = 0; c < 4; c++) O2[i][c] = make_float2(0.f, 0.f);
    }

    const float scale = 0.08838834764831845f;

    for (int n0 = 0; n0 < Sq; n0 += 128) {
        __syncthreads();
#pragma unroll
        for (int i = 0; i < 16; i++) {
            int idx = tid + i * 256;
            int r = idx >> 5, c = (idx & 31) * 4;
            float4 k4 = *reinterpret_cast<const float4*>(kptr + (size_t)(n0 + r) * HDc + c);
            Ks[r * ST + c] = k4.x; Ks[r * ST + c + 1] = k4.y;
            Ks[r * ST + c + 2] = k4.z; Ks[r * ST + c + 3] = k4.w;
            *reinterpret_cast<float4*>(Vs + r * 128 + c) =
                *reinterpret_cast<const float4*>(vptr + (size_t)(n0 + r) * HDc + c);
        }
        __syncthreads();

        float2 s2[8][4];
#pragma unroll
        for (int i = 0; i < 8; i++)
#pragma unroll
            for (int c = 0; c < 4; c++) s2[i][c] = make_float2(0.f, 0.f);

        for (int d = 0; d < HDc; d += 4) {
            float4 q4[8];
#pragma unroll
            for (int i = 0; i < 8; i++)
                q4[i] = *reinterpret_cast<const float4*>(&Qs[(8 * ti + i) * ST + d]);
#pragma unroll
            for (int c = 0; c < 4; c++) {
                float4 ka = *reinterpret_cast<const float4*>(&Ks[(tn + 16 * (2 * c)) * ST + d]);
                float4 kb = *reinterpret_cast<const float4*>(&Ks[(tn + 16 * (2 * c + 1)) * ST + d]);
#pragma unroll
                for (int i = 0; i < 8; i++) {
                    s2[i][c] = ffma2(make_float2(q4[i].x, q4[i].x), make_float2(ka.x, kb.x), s2[i][c]);
                    s2[i][c] = ffma2(make_float2(q4[i].y, q4[i].y), make_float2(ka.y, kb.y), s2[i][c]);
                    s2[i][c] = ffma2(make_float2(q4[i].z, q4[i].z), make_float2(ka.z, kb.z), s2[i][c]);
                    s2[i][c] = ffma2(make_float2(q4[i].w, q4[i].w), make_float2(ka.w, kb.w), s2[i][c]);
                }
            }
        }

        float corr[8];
#pragma unroll
        for (int i = 0; i < 8; i++) {
            float mt = fmaxf(fmaxf(fmaxf(s2[i][0].x, s2[i][0].y), fmaxf(s2[i][1].x, s2[i][1].y)),
                             fmaxf(fmaxf(s2[i][2].x, s2[i][2].y), fmaxf(s2[i][3].x, s2[i][3].y)));
            mt *= scale;
#pragma unroll
            for (int off = 1; off < 16; off <<= 1)
                mt = fmaxf(mt, __shfl_xor_sync(0xffffffffu, mt, off));
            float mnew = fmaxf(mrow[i], mt);
            corr[i] = __expf(mrow[i] - mnew);
            mrow[i] = mnew;
        }
#pragma unroll
        for (int i = 0; i < 8; i++) {
            float sum = 0.f;
#pragma unroll
            for (int c = 0; c < 4; c++) {
                float px = __expf(s2[i][c].x * scale - mrow[i]);
                float py = __expf(s2[i][c].y * scale - mrow[i]);
                s2[i][c].x = px; s2[i][c].y = py;
                sum += px + py;
            }
#pragma unroll
            for (int off = 1; off < 16; off <<= 1)
                sum += __shfl_xor_sync(0xffffffffu, sum, off);
            lrow[i] = lrow[i] * corr[i] + sum;
        }

        __syncthreads();

#pragma unroll
        for (int i = 0; i < 8; i++) {
            int r = 8 * ti + i;
#pragma unroll
            for (int c = 0; c < 4; c++) {
                Ps[r * ST + tn + 16 * (2 * c)]     = s2[i][c].x;
                Ps[r * ST + tn + 16 * (2 * c + 1)] = s2[i][c].y;
            }
        }
        __syncwarp();

#pragma unroll
        for (int i = 0; i < 8; i++)
#pragma unroll
            for (int c = 0; c < 4; c++) { O2[i][c].x *= corr[i]; O2[i][c].y *= corr[i]; }

        for (int k = 0; k < 128; k += 4) {
            float4 p4[8];
#pragma unroll
            for (int i = 0; i < 8; i++)
                p4[i] = *reinterpret_cast<const float4*>(&Ps[(8 * ti + i) * ST + k]);
#pragma unroll
            for (int c = 0; c < 4; c++) {
                int ca = tn + 16 * (2 * c), cb = tn + 16 * (2 * c + 1);
                float2 v0 = make_float2(Vs[(k + 0) * 128 + ca], Vs[(k + 0) * 128 + cb]);
                float2 v1 = make_float2(Vs[(k + 1) * 128 + ca], Vs[(k + 1) * 128 + cb]);
                float2 v2 = make_float2(Vs[(k + 2) * 128 + ca], Vs[(k + 2) * 128 + cb]);
                float2 v3 = make_float2(Vs[(k + 3) * 128 + ca], Vs[(k + 3) * 128 + cb]);
#pragma unroll
                for (int i = 0; i < 8; i++) {
                    O2[i][c] = ffma2(make_float2(p4[i].x, p4[i].x), v0, O2[i][c]);
                    O2[i][c] = ffma2(make_float2(p4[i].y, p4[i].y), v1, O2[i][c]);
                    O2[i][c] = ffma2(make_float2(p4[i].z, p4[i].z), v2, O2[i][c]);
                    O2[i][c] = ffma2(make_float2(p4[i].w, p4[i].w), v3, O2[i][c]);
                }
            }
        }
    }

#pragma unroll
    for (int i = 0; i < 8; i++) {
        float inv = 1.0f / lrow[i];
        int srow = q0 + 8 * ti + i;
        float* optr = ctx + ((size_t)b * Sq + srow) * (size_t)(NHc * HDc) + h * HDc;
#pragma unroll
        for (int c = 0; c < 4; c++) {
            optr[tn + 16 * (2 * c)]     = O2[i][c].x * inv;
            optr[tn + 16 * (2 * c + 1)] = O2[i][c].y * inv;
        }
    }
}

// ---------------------------------------------------------------------------
extern "C" void kernel_launch(void* const* d_in, const int* in_sizes, int n_in,
                              void* d_out, int out_size)
{
    const float* hidden = (const float*)d_in[0];
    const float* cosp   = (const float*)d_in[1];
    const float* sinp   = (const float*)d_in[2];
    const float* Wq     = (const float*)d_in[3];
    const float* bq     = (const float*)d_in[4];
    const float* Wk     = (const float*)d_in[5];
    const float* bk     = (const float*)d_in[6];
    const float* Wv     = (const float*)d_in[7];
    const float* bv     = (const float*)d_in[8];
    const float* Wo     = (const float*)d_in[9];
    float* out = (float*)d_out;

    float *qb, *kb, *vb, *cb;
    __nv_bfloat16 *ahi, *alo, *bhi, *blo;
    cudaGetSymbolAddress((void**)&qb, g_Q);
    cudaGetSymbolAddress((void**)&kb, g_K);
    cudaGetSymbolAddress((void**)&vb, g_V);
    cudaGetSymbolAddress((void**)&cb, g_ctx);
    cudaGetSymbolAddress((void**)&ahi, g_Ahi);
    cudaGetSymbolAddress((void**)&alo, g_Alo);
    cudaGetSymbolAddress((void**)&bhi, g_Bhi);
    cudaGetSymbolAddress((void**)&blo, g_Blo);

    cudaFuncSetAttribute(gemm_mma<0>, cudaFuncAttributeMaxDynamicSharedMemorySize, GSMEM);
    cudaFuncSetAttribute(gemm_mma<1>, cudaFuncAttributeMaxDynamicSharedMemorySize, GSMEM);
    cudaFuncSetAttribute(flash_kernel, cudaFuncAttributeMaxDynamicSharedMemorySize, FL_SMEM);

    // 1. prep: split(hidden) + transpose-split(Wq, Wk, Wv)
    prep_kernel<<<16384 + 16384 + 4096 + 4096, 256>>>(hidden, ahi, alo, Wq, Wk, Wv, bhi, blo);

    // 2. fused QKV projection (N = 6144)
    gemm_mma<1><<<dim3(NQKV / 128, 32), 256, GSMEM>>>(ahi, alo, bhi, blo,
                                                      bq, bk, bv, qb, kb, vb, NQKV);

    // 3. RoPE on Q and K in one launch
    {
        int tot = Bc * NHc * Sq * 64 + Bc * NKVc * Sq * 64;
        rope2_kernel<<<(tot + 255) / 256, 256>>>(qb, kb, cosp, sinp);
    }

    // 4. flash attention  <-- profiled (launch #4)
    flash_kernel<<<dim3(Sq / 128, NHc, Bc), 256, FL_SMEM>>>(qb, kb, vb, cb);

    // 5-7. output projection
    split_kernel<<<16384, 256>>>(cb, ahi, alo);
    tsplit_kernel<<<16384, 256>>>(Wo, bhi, blo);
    gemm_mma<0><<<dim3(32, 32), 256, GSMEM>>>(ahi, alo, bhi, blo,
                                              nullptr, nullptr, nullptr,
                                              out, nullptr, nullptr, 4096);
}